// round 1
// baseline (speedup 1.0000x reference)
#include <cuda_runtime.h>

#define BATCH 8
#define NN    4096
#define INC   256
#define HIDC  512
#define OUTC  256

// Scratch (no cudaMalloc allowed): d^{-1/2}, M1, h, M2
__device__ float g_dinv[BATCH * NN];                 // 128 KB
__device__ float g_m1  [(size_t)BATCH * NN * HIDC];  // 64 MB
__device__ float g_h   [(size_t)BATCH * NN * HIDC];  // 64 MB
__device__ float g_m2  [(size_t)BATCH * NN * OUTC];  // 32 MB

// ---------------------------------------------------------------------------
// Kernel 1: per-row degree of A_hat = A + I, store rsqrt(deg)
// one block per row, 256 threads, float4 loads
// ---------------------------------------------------------------------------
__global__ void deg_kernel(const float* __restrict__ A, float* __restrict__ dinv) {
    int row = blockIdx.x;  // 0 .. B*N-1
    const float4* Arow = (const float4*)(A + (size_t)row * NN);
    float s = 0.f;
    #pragma unroll 4
    for (int i = threadIdx.x; i < NN / 4; i += 256) {
        float4 v = Arow[i];
        s += (v.x + v.y) + (v.z + v.w);
    }
    __shared__ float red[8];
    #pragma unroll
    for (int o = 16; o; o >>= 1) s += __shfl_down_sync(~0u, s, o);
    if ((threadIdx.x & 31) == 0) red[threadIdx.x >> 5] = s;
    __syncthreads();
    if (threadIdx.x < 8) {
        float t = red[threadIdx.x];
        #pragma unroll
        for (int o = 4; o; o >>= 1) t += __shfl_down_sync(0xffu, t, o);
        if (threadIdx.x == 0) dinv[row] = rsqrtf(t + 1.0f);  // + self loop
    }
}

// ---------------------------------------------------------------------------
// Kernel 2/4: M = d ⊙ (X @ W).   X: [B*N, K] row-major, W: [K, NCOL]
// 64x64 tile, BK=16, 256 threads, 4x4 micro-tile
// ---------------------------------------------------------------------------
template <int K, int NCOL>
__global__ void __launch_bounds__(256) xw_kernel(
    const float* __restrict__ X, const float* __restrict__ W,
    const float* __restrict__ dinv, float* __restrict__ out)
{
    const int BM = 64, BN = 64, BK = 16;
    __shared__ __align__(16) float Xs[BK][BM + 4];
    __shared__ __align__(16) float Ws[BK][BN];
    int m0 = blockIdx.y * BM;
    int n0 = blockIdx.x * BN;
    int t  = threadIdx.x;
    int ty = t >> 4, tx = t & 15;
    float acc[4][4] = {};

    for (int k0 = 0; k0 < K; k0 += BK) {
        {   // X tile 64x16: 256 float4, transpose into Xs[k][m]
            int row = t >> 2, kc = (t & 3) * 4;
            float4 v = *(const float4*)(X + (size_t)(m0 + row) * K + k0 + kc);
            Xs[kc + 0][row] = v.x; Xs[kc + 1][row] = v.y;
            Xs[kc + 2][row] = v.z; Xs[kc + 3][row] = v.w;
        }
        {   // W tile 16x64: 256 float4 direct
            int kr = t >> 4, c4 = (t & 15) * 4;
            *(float4*)&Ws[kr][c4] = *(const float4*)(W + (size_t)(k0 + kr) * NCOL + n0 + c4);
        }
        __syncthreads();
        #pragma unroll
        for (int k = 0; k < BK; k++) {
            float a[4], b[4];
            *(float4*)a = *(float4*)&Xs[k][ty * 4];
            *(float4*)b = *(float4*)&Ws[k][tx * 4];
            #pragma unroll
            for (int i = 0; i < 4; i++)
                #pragma unroll
                for (int j = 0; j < 4; j++)
                    acc[i][j] += a[i] * b[j];
        }
        __syncthreads();
    }
    #pragma unroll
    for (int i = 0; i < 4; i++) {
        int m = m0 + ty * 4 + i;
        float d = dinv[m];
        float4 v = { acc[i][0] * d, acc[i][1] * d, acc[i][2] * d, acc[i][3] * d };
        *(float4*)(out + (size_t)m * NCOL + n0 + tx * 4) = v;
    }
}

// ---------------------------------------------------------------------------
// Kernel 3/5: out = epilogue( A_b @ M_b + M_b )  per batch b
// epilogue: val = d[m]*acc + bias[n]; optional ReLU
// 128x128 tile, BK=16, 256 threads, 8x8 micro-tile (split 4+4 for banks)
// ---------------------------------------------------------------------------
template <int NCOL, bool RELU>
__global__ void __launch_bounds__(256, 2) agemm_kernel(
    const float* __restrict__ A, const float* __restrict__ M,
    const float* __restrict__ dinv, const float* __restrict__ bias,
    float* __restrict__ out)
{
    const int BM = 128, BN = 128, BK = 16;
    __shared__ __align__(16) float As[BK][BM + 4];
    __shared__ __align__(16) float Bs[BK][BN];

    int b  = blockIdx.z;
    const float* Ab = A + (size_t)b * NN * NN;
    const float* Mb = M + (size_t)b * NN * NCOL;
    float*       Ob = out + (size_t)b * NN * NCOL;
    const float* db = dinv + b * NN;

    int m0 = blockIdx.y * BM, n0 = blockIdx.x * BN;
    int t  = threadIdx.x;
    int ty = t >> 4, tx = t & 15;
    float acc[8][8] = {};

    for (int k0 = 0; k0 < NN; k0 += BK) {
        // A tile: 128 x 16 -> 512 float4; transpose into As[k][m]
        #pragma unroll
        for (int ff = 0; ff < 2; ff++) {
            int f = t + ff * 256;
            int row = f >> 2, kc = (f & 3) * 4;
            float4 v = *(const float4*)(Ab + (size_t)(m0 + row) * NN + k0 + kc);
            As[kc + 0][row] = v.x; As[kc + 1][row] = v.y;
            As[kc + 2][row] = v.z; As[kc + 3][row] = v.w;
        }
        // M tile: 16 x 128 -> 512 float4 direct
        #pragma unroll
        for (int ff = 0; ff < 2; ff++) {
            int f = t + ff * 256;
            int kr = f >> 5, c4 = (f & 31) * 4;
            *(float4*)&Bs[kr][c4] = *(const float4*)(Mb + (size_t)(k0 + kr) * NCOL + n0 + c4);
        }
        __syncthreads();
        #pragma unroll
        for (int k = 0; k < BK; k++) {
            float a[8], bb[8];
            *(float4*)&a[0]  = *(float4*)&As[k][ty * 4];
            *(float4*)&a[4]  = *(float4*)&As[k][64 + ty * 4];
            *(float4*)&bb[0] = *(float4*)&Bs[k][tx * 4];
            *(float4*)&bb[4] = *(float4*)&Bs[k][64 + tx * 4];
            #pragma unroll
            for (int i = 0; i < 8; i++)
                #pragma unroll
                for (int j = 0; j < 8; j++)
                    acc[i][j] += a[i] * bb[j];
        }
        __syncthreads();
    }

    // epilogue: + self-loop M[m,n], * d[m], + bias[n], (relu)
    #pragma unroll
    for (int ig = 0; ig < 2; ig++) {
        #pragma unroll
        for (int i = 0; i < 4; i++) {
            int m = m0 + ig * 64 + ty * 4 + i;
            float d = db[m];
            #pragma unroll
            for (int jg = 0; jg < 2; jg++) {
                int n = n0 + jg * 64 + tx * 4;
                float4 self = *(const float4*)(Mb + (size_t)m * NCOL + n);
                float4 bs   = *(const float4*)(bias + n);
                float r0 = (acc[ig * 4 + i][jg * 4 + 0] + self.x) * d + bs.x;
                float r1 = (acc[ig * 4 + i][jg * 4 + 1] + self.y) * d + bs.y;
                float r2 = (acc[ig * 4 + i][jg * 4 + 2] + self.z) * d + bs.z;
                float r3 = (acc[ig * 4 + i][jg * 4 + 3] + self.w) * d + bs.w;
                if (RELU) {
                    r0 = fmaxf(r0, 0.f); r1 = fmaxf(r1, 0.f);
                    r2 = fmaxf(r2, 0.f); r3 = fmaxf(r3, 0.f);
                }
                float4 v = { r0, r1, r2, r3 };
                *(float4*)(Ob + (size_t)m * NCOL + n) = v;
            }
        }
    }
}

// ---------------------------------------------------------------------------
// Launch
// inputs (metadata order): x[B,N,256], A[B,N,N], W1[256,512], b1[512],
//                          W2[512,256], b2[256] ; out: [B,N,256] f32
// ---------------------------------------------------------------------------
extern "C" void kernel_launch(void* const* d_in, const int* in_sizes, int n_in,
                              void* d_out, int out_size)
{
    const float* x  = (const float*)d_in[0];
    const float* A  = (const float*)d_in[1];
    const float* W1 = (const float*)d_in[2];
    const float* b1 = (const float*)d_in[3];
    const float* W2 = (const float*)d_in[4];
    const float* b2 = (const float*)d_in[5];
    float* out = (float*)d_out;

    float* dinv; cudaGetSymbolAddress((void**)&dinv, g_dinv);
    float* m1;   cudaGetSymbolAddress((void**)&m1,   g_m1);
    float* h;    cudaGetSymbolAddress((void**)&h,    g_h);
    float* m2;   cudaGetSymbolAddress((void**)&m2,   g_m2);

    // 1. d = rsqrt(rowsum(A)+1)
    deg_kernel<<<BATCH * NN, 256>>>(A, dinv);

    // 2. M1 = d ⊙ (x @ W1)
    {
        dim3 grid(HIDC / 64, BATCH * NN / 64);
        xw_kernel<INC, HIDC><<<grid, 256>>>(x, W1, dinv, m1);
    }
    // 3. h = relu(d ⊙ (A@M1 + M1) + b1)
    {
        dim3 grid(HIDC / 128, NN / 128, BATCH);
        agemm_kernel<HIDC, true><<<grid, 256>>>(A, m1, dinv, b1, h);
    }
    // 4. M2 = d ⊙ (h @ W2)
    {
        dim3 grid(OUTC / 64, BATCH * NN / 64);
        xw_kernel<HIDC, OUTC><<<grid, 256>>>(h, W2, dinv, m2);
    }
    // 5. out = d ⊙ (A@M2 + M2) + b2
    {
        dim3 grid(OUTC / 128, NN / 128, BATCH);
        agemm_kernel<OUTC, false><<<grid, 256>>>(A, m2, dinv, b2, out);
    }
}

// round 12
// speedup vs baseline: 3.5770x; 3.5770x over previous
#include <cuda_runtime.h>
#include <cuda_fp16.h>
#include <cstdint>

#define BATCH 8
#define NN    4096
#define INC   256
#define HIDC  512
#define OUTC  256

// Scratch (no cudaMalloc allowed)
__device__ float  g_dinv[BATCH * NN];                   // 128 KB
__device__ __half g_Ah [(size_t)BATCH * NN * NN];       // 256 MB (fp16 A)
__device__ float  g_m1 [(size_t)BATCH * NN * HIDC];     // 64 MB  (fp32 [m,h])
__device__ __half g_m1t[(size_t)BATCH * HIDC * NN];     // 32 MB  (fp16 transposed)
__device__ float  g_h  [(size_t)BATCH * NN * HIDC];     // 64 MB
__device__ float  g_m2 [(size_t)BATCH * NN * OUTC];     // 32 MB
__device__ __half g_m2t[(size_t)BATCH * OUTC * NN];     // 16 MB

// ---------------------------------------------------------------------------
// helpers
// ---------------------------------------------------------------------------
__device__ __forceinline__ uint32_t smem_u32(const void* p) {
    uint32_t a;
    asm("{ .reg .u64 t; cvta.to.shared.u64 t, %1; cvt.u32.u64 %0, t; }" : "=r"(a) : "l"(p));
    return a;
}
__device__ __forceinline__ void cp16(uint32_t s, const void* g) {
    asm volatile("cp.async.cg.shared.global [%0], [%1], 16;" :: "r"(s), "l"(g) : "memory");
}
__device__ __forceinline__ void cp_commit() {
    asm volatile("cp.async.commit_group;" ::: "memory");
}
template <int N> __device__ __forceinline__ void cp_wait() {
    asm volatile("cp.async.wait_group %0;" :: "n"(N) : "memory");
}
// fp16 MMA m16n8k16, fp32 accumulate (sm_80+ baseline PTX -> HMMA on Blackwell)
__device__ __forceinline__ void mma16816(float* c, const uint32_t* a, const uint32_t* b) {
    asm volatile(
        "mma.sync.aligned.m16n8k16.row.col.f32.f16.f16.f32 "
        "{%0,%1,%2,%3}, {%4,%5,%6,%7}, {%8,%9}, {%0,%1,%2,%3};"
        : "+f"(c[0]), "+f"(c[1]), "+f"(c[2]), "+f"(c[3])
        : "r"(a[0]), "r"(a[1]), "r"(a[2]), "r"(a[3]), "r"(b[0]), "r"(b[1]));
}

// ---------------------------------------------------------------------------
// Kernel 1: d^{-1/2} of A_hat = A + I, and fp16 copy of A
// ---------------------------------------------------------------------------
__global__ void deg_kernel(const float* __restrict__ A, float* __restrict__ dinv,
                           __half* __restrict__ Ah) {
    int row = blockIdx.x;
    const float4* Arow = (const float4*)(A + (size_t)row * NN);
    uint2*        Hrow = (uint2*)(Ah + (size_t)row * NN);
    float s = 0.f;
    #pragma unroll 4
    for (int i = threadIdx.x; i < NN / 4; i += 256) {
        float4 v = Arow[i];
        s += (v.x + v.y) + (v.z + v.w);
        __half2 h0 = __floats2half2_rn(v.x, v.y);
        __half2 h1 = __floats2half2_rn(v.z, v.w);
        uint2 pk = { *(uint32_t*)&h0, *(uint32_t*)&h1 };
        Hrow[i] = pk;
    }
    __shared__ float red[8];
    #pragma unroll
    for (int o = 16; o; o >>= 1) s += __shfl_down_sync(~0u, s, o);
    if ((threadIdx.x & 31) == 0) red[threadIdx.x >> 5] = s;
    __syncthreads();
    if (threadIdx.x < 8) {
        float t = red[threadIdx.x];
        #pragma unroll
        for (int o = 4; o; o >>= 1) t += __shfl_down_sync(0xffu, t, o);
        if (threadIdx.x == 0) dinv[row] = rsqrtf(t + 1.0f);
    }
}

// ---------------------------------------------------------------------------
// Kernel 2/4: M = d ⊙ (X @ W); fp32 [m,n] + fp16 transposed [n,j] per batch
// ---------------------------------------------------------------------------
template <int K, int NCOL>
__global__ void __launch_bounds__(256) xw_kernel(
    const float* __restrict__ X, const float* __restrict__ W,
    const float* __restrict__ dinv, float* __restrict__ out,
    __half* __restrict__ outT)
{
    const int BM = 64, BN = 64, BK = 16;
    __shared__ __align__(16) float Xs[BK][BM + 4];
    __shared__ __align__(16) float Ws[BK][BN];
    int m0 = blockIdx.y * BM;
    int n0 = blockIdx.x * BN;
    int t  = threadIdx.x;
    int ty = t >> 4, tx = t & 15;
    float acc[4][4] = {};

    for (int k0 = 0; k0 < K; k0 += BK) {
        {
            int row = t >> 2, kc = (t & 3) * 4;
            float4 v = *(const float4*)(X + (size_t)(m0 + row) * K + k0 + kc);
            Xs[kc + 0][row] = v.x; Xs[kc + 1][row] = v.y;
            Xs[kc + 2][row] = v.z; Xs[kc + 3][row] = v.w;
        }
        {
            int kr = t >> 4, c4 = (t & 15) * 4;
            *(float4*)&Ws[kr][c4] = *(const float4*)(W + (size_t)(k0 + kr) * NCOL + n0 + c4);
        }
        __syncthreads();
        #pragma unroll
        for (int k = 0; k < BK; k++) {
            float a[4], b[4];
            *(float4*)a = *(float4*)&Xs[k][ty * 4];
            *(float4*)b = *(float4*)&Ws[k][tx * 4];
            #pragma unroll
            for (int i = 0; i < 4; i++)
                #pragma unroll
                for (int j = 0; j < 4; j++)
                    acc[i][j] += a[i] * b[j];
        }
        __syncthreads();
    }
    #pragma unroll
    for (int i = 0; i < 4; i++) {
        int m = m0 + ty * 4 + i;
        float d = dinv[m];
        int bb = m >> 12;          // batch (NN = 4096)
        int jj = m & (NN - 1);     // node index in batch
        float4 v = { acc[i][0] * d, acc[i][1] * d, acc[i][2] * d, acc[i][3] * d };
        *(float4*)(out + (size_t)m * NCOL + n0 + tx * 4) = v;
        #pragma unroll
        for (int j = 0; j < 4; j++) {
            int n = n0 + tx * 4 + j;
            outT[((size_t)bb * NCOL + n) * NN + jj] = __float2half_rn(acc[i][j] * d);
        }
    }
}

// ---------------------------------------------------------------------------
// Kernel 3/5: out = epi( A_b @ M_b + M_b ) via mma.sync m16n8k16 fp16->fp32
// Ah : fp16 A [NN, NN] per batch (row-major, k contiguous)
// Mt : fp16 transposed operand [NCOL, NN] per batch (n rows, k contiguous)
// Mn : fp32 [NN, NCOL] (self-loop); epilogue: (acc+self)*d + bias (, relu)
// 128x128 CTA tile, 8 warps (32x64 each), BK=64 halves, 3-stage cp.async
// ---------------------------------------------------------------------------
template <int NCOL, bool RELU>
__global__ void __launch_bounds__(256, 2) agemm_mma(
    const __half* __restrict__ Ah, const __half* __restrict__ Mt,
    const float* __restrict__ Mn, const float* __restrict__ dinv,
    const float* __restrict__ bias, float* __restrict__ out)
{
    constexpr int BM = 128, BN = 128, BK = 64, S = 3;
    constexpr int ITERS = NN / BK;                   // 64
    constexpr int ROWB  = BK * 2 + 16;               // 144 bytes/row (pad: conflict-free)
    constexpr int TILE  = BM * ROWB;                 // 18432 B
    constexpr int STAGE = 2 * TILE;                  // 36864 B

    extern __shared__ __align__(16) char smem[];
    uint32_t sbase = smem_u32(smem);

    const int tid  = threadIdx.x;
    const int wid  = tid >> 5, lane = tid & 31;
    const int wm   = wid & 3, wn = wid >> 2;         // warp grid 4x2 (m x n)
    const int gid  = lane >> 2, t4 = lane & 3;

    const int b  = blockIdx.z;
    const int m0 = blockIdx.y * BM, n0 = blockIdx.x * BN;
    const __half* Ab  = Ah + (size_t)b * NN * NN;
    const __half* Mtb = Mt + (size_t)b * NCOL * NN;
    const float*  Mnb = Mn + (size_t)b * NN * NCOL;
    const float*  db  = dinv + b * NN;

    // per-thread gmem->smem slice: 4 x 16B per operand tile
    // slot = tid + i*256 ; row = slot>>3 (0..127), qh = (slot&7)*8 halves
    auto issue_loads = [&](int chunk, int stage) {
        int k0h = chunk * BK;
        uint32_t a_s = sbase + stage * STAGE;
        uint32_t b_s = a_s + TILE;
        #pragma unroll
        for (int i = 0; i < 4; i++) {
            int slot = tid + i * 256;
            int row  = slot >> 3;
            int qh   = (slot & 7) * 8;               // half index within chunk
            cp16(a_s + row * ROWB + qh * 2, Ab  + (size_t)(m0 + row) * NN + k0h + qh);
            cp16(b_s + row * ROWB + qh * 2, Mtb + (size_t)(n0 + row) * NN + k0h + qh);
        }
    };

    float acc[2][8][4] = {};                          // mt, nt, frag

    // prologue: S-1 stages in flight
    issue_loads(0, 0); cp_commit();
    issue_loads(1, 1); cp_commit();

    for (int it = 0; it < ITERS; it++) {
        int stage = it % S;
        if (it + S - 1 < ITERS) issue_loads(it + S - 1, (it + S - 1) % S);
        cp_commit();                                  // real or empty
        cp_wait<S - 1>();                             // chunk `it` resident
        __syncthreads();

        const char* As = smem + stage * STAGE;
        const char* Bs = As + TILE;
        #pragma unroll
        for (int ks = 0; ks < 4; ks++) {
            int k0 = ks * 16;                         // halves
            uint32_t afr[2][4], bfr[8][2];
            #pragma unroll
            for (int mt = 0; mt < 2; mt++) {
                const char* base = As + (wm * 32 + mt * 16 + gid) * ROWB + (k0 + 2 * t4) * 2;
                afr[mt][0] = *(const uint32_t*)(base);
                afr[mt][1] = *(const uint32_t*)(base + 8 * ROWB);
                afr[mt][2] = *(const uint32_t*)(base + 16);
                afr[mt][3] = *(const uint32_t*)(base + 8 * ROWB + 16);
            }
            #pragma unroll
            for (int nt = 0; nt < 8; nt++) {
                const char* base = Bs + (wn * 64 + nt * 8 + gid) * ROWB + (k0 + 2 * t4) * 2;
                bfr[nt][0] = *(const uint32_t*)(base);
                bfr[nt][1] = *(const uint32_t*)(base + 16);
            }
            #pragma unroll
            for (int mt = 0; mt < 2; mt++)
                #pragma unroll
                for (int nt = 0; nt < 8; nt++)
                    mma16816(acc[mt][nt], afr[mt], bfr[nt]);
        }
        __syncthreads();                              // readers done before stage reuse
    }

    // epilogue: (acc + self)*d + bias (, relu)
    float* Ob = out + (size_t)b * NN * NCOL;
    #pragma unroll
    for (int mt = 0; mt < 2; mt++) {
        int mA = m0 + wm * 32 + mt * 16 + gid;
        int mB = mA + 8;
        float dA = db[mA], dB = db[mB];
        #pragma unroll
        for (int nt = 0; nt < 8; nt++) {
            int n = n0 + wn * 64 + nt * 8 + 2 * t4;
            float2 bs = *(const float2*)(bias + n);
            float2 sA = *(const float2*)(Mnb + (size_t)mA * NCOL + n);
            float2 sB = *(const float2*)(Mnb + (size_t)mB * NCOL + n);
            float2 vA, vB;
            vA.x = (acc[mt][nt][0] + sA.x) * dA + bs.x;
            vA.y = (acc[mt][nt][1] + sA.y) * dA + bs.y;
            vB.x = (acc[mt][nt][2] + sB.x) * dB + bs.x;
            vB.y = (acc[mt][nt][3] + sB.y) * dB + bs.y;
            if (RELU) {
                vA.x = fmaxf(vA.x, 0.f); vA.y = fmaxf(vA.y, 0.f);
                vB.x = fmaxf(vB.x, 0.f); vB.y = fmaxf(vB.y, 0.f);
            }
            *(float2*)(Ob + (size_t)mA * NCOL + n) = vA;
            *(float2*)(Ob + (size_t)mB * NCOL + n) = vB;
        }
    }
}

// ---------------------------------------------------------------------------
// Launch
// ---------------------------------------------------------------------------
extern "C" void kernel_launch(void* const* d_in, const int* in_sizes, int n_in,
                              void* d_out, int out_size)
{
    const float* x  = (const float*)d_in[0];
    const float* A  = (const float*)d_in[1];
    const float* W1 = (const float*)d_in[2];
    const float* b1 = (const float*)d_in[3];
    const float* W2 = (const float*)d_in[4];
    const float* b2 = (const float*)d_in[5];
    float* out = (float*)d_out;

    float*  dinv; cudaGetSymbolAddress((void**)&dinv, g_dinv);
    __half* Ah;   cudaGetSymbolAddress((void**)&Ah,   g_Ah);
    float*  m1;   cudaGetSymbolAddress((void**)&m1,   g_m1);
    __half* m1t;  cudaGetSymbolAddress((void**)&m1t,  g_m1t);
    float*  h;    cudaGetSymbolAddress((void**)&h,    g_h);
    float*  m2;   cudaGetSymbolAddress((void**)&m2,   g_m2);
    __half* m2t;  cudaGetSymbolAddress((void**)&m2t,  g_m2t);

    constexpr int SMEM_BYTES = 3 * 2 * 128 * 144;    // 110592
    cudaFuncSetAttribute(agemm_mma<HIDC, true>,
                         cudaFuncAttributeMaxDynamicSharedMemorySize, SMEM_BYTES);
    cudaFuncSetAttribute(agemm_mma<OUTC, false>,
                         cudaFuncAttributeMaxDynamicSharedMemorySize, SMEM_BYTES);

    // 1. degrees + fp16 A
    deg_kernel<<<BATCH * NN, 256>>>(A, dinv, Ah);

    // 2. M1 = d ⊙ (x @ W1)  (+ fp16 transposed copy)
    {
        dim3 grid(HIDC / 64, BATCH * NN / 64);
        xw_kernel<INC, HIDC><<<grid, 256>>>(x, W1, dinv, m1, m1t);
    }
    // 3. h = relu(d ⊙ (A@M1 + M1) + b1)
    {
        dim3 grid(HIDC / 128, NN / 128, BATCH);
        agemm_mma<HIDC, true><<<grid, 256, SMEM_BYTES>>>(Ah, m1t, m1, dinv, b1, h);
    }
    // 4. M2 = d ⊙ (h @ W2)  (+ fp16 transposed copy)
    {
        dim3 grid(OUTC / 64, BATCH * NN / 64);
        xw_kernel<HIDC, OUTC><<<grid, 256>>>(h, W2, dinv, m2, m2t);
    }
    // 5. out = d ⊙ (A@M2 + M2) + b2
    {
        dim3 grid(OUTC / 128, NN / 128, BATCH);
        agemm_mma<OUTC, false><<<grid, 256, SMEM_BYTES>>>(Ah, m2t, m2, dinv, b2, out);
    }
}

// round 16
// speedup vs baseline: 5.5556x; 1.5531x over previous
#include <cuda_runtime.h>
#include <cuda_fp16.h>
#include <cstdint>

#define BATCH 8
#define NN    4096
#define INC   256
#define HIDC  512
#define OUTC  256

// Scratch (no cudaMalloc allowed)
__device__ float  g_dinv[BATCH * NN];                   // 128 KB
__device__ __half g_Ah [(size_t)BATCH * NN * NN];       // 256 MB fp16 A
__device__ __half g_xh [(size_t)BATCH * NN * INC];      // 16 MB fp16 x
__device__ __half g_w1t[HIDC * INC];                    // 256 KB W1^T fp16
__device__ __half g_w2t[OUTC * HIDC];                   // 256 KB W2^T fp16
__device__ float  g_m1 [(size_t)BATCH * NN * HIDC];     // 64 MB fp32 M1 (self-loop)
__device__ __half g_m1t[(size_t)BATCH * HIDC * NN];     // 32 MB fp16 M1^T
__device__ __half g_hh [(size_t)BATCH * NN * HIDC];     // 32 MB fp16 h
__device__ float  g_m2 [(size_t)BATCH * NN * OUTC];     // 32 MB fp32 M2
__device__ __half g_m2t[(size_t)BATCH * OUTC * NN];     // 16 MB fp16 M2^T

// ---------------------------------------------------------------------------
// helpers
// ---------------------------------------------------------------------------
__device__ __forceinline__ uint32_t smem_u32(const void* p) {
    uint32_t a;
    asm("{ .reg .u64 t; cvta.to.shared.u64 t, %1; cvt.u32.u64 %0, t; }" : "=r"(a) : "l"(p));
    return a;
}
__device__ __forceinline__ void cp16(uint32_t s, const void* g) {
    asm volatile("cp.async.cg.shared.global [%0], [%1], 16;" :: "r"(s), "l"(g) : "memory");
}
__device__ __forceinline__ void cp_commit() {
    asm volatile("cp.async.commit_group;" ::: "memory");
}
template <int N> __device__ __forceinline__ void cp_wait() {
    asm volatile("cp.async.wait_group %0;" :: "n"(N) : "memory");
}
__device__ __forceinline__ void mma16816(float* c, const uint32_t* a, const uint32_t* b) {
    asm volatile(
        "mma.sync.aligned.m16n8k16.row.col.f32.f16.f16.f32 "
        "{%0,%1,%2,%3}, {%4,%5,%6,%7}, {%8,%9}, {%0,%1,%2,%3};"
        : "+f"(c[0]), "+f"(c[1]), "+f"(c[2]), "+f"(c[3])
        : "r"(a[0]), "r"(a[1]), "r"(a[2]), "r"(a[3]), "r"(b[0]), "r"(b[1]));
}
__device__ __forceinline__ void ldsm_x4(uint32_t* r, uint32_t addr) {
    asm volatile("ldmatrix.sync.aligned.m8n8.x4.shared.b16 {%0,%1,%2,%3}, [%4];"
                 : "=r"(r[0]), "=r"(r[1]), "=r"(r[2]), "=r"(r[3]) : "r"(addr));
}

// tile constants shared by both GEMM kernels
#define ROWB  144              // 128 halves + 16B pad: LDSM conflict-free
#define TILEB (128 * ROWB)
#define STAGEB (2 * TILEB)
#define SMEM_BYTES (3 * STAGEB)   // 110592

// ---------------------------------------------------------------------------
// Kernel 1: d^{-1/2} of A_hat = A + I, and fp16 copy of A
// ---------------------------------------------------------------------------
__global__ void deg_kernel(const float* __restrict__ A, float* __restrict__ dinv,
                           __half* __restrict__ Ah) {
    int row = blockIdx.x;
    const float4* Arow = (const float4*)(A + (size_t)row * NN);
    uint2*        Hrow = (uint2*)(Ah + (size_t)row * NN);
    float s = 0.f;
    #pragma unroll 4
    for (int i = threadIdx.x; i < NN / 4; i += 256) {
        float4 v = Arow[i];
        s += (v.x + v.y) + (v.z + v.w);
        __half2 h0 = __floats2half2_rn(v.x, v.y);
        __half2 h1 = __floats2half2_rn(v.z, v.w);
        uint2 pk = { *(uint32_t*)&h0, *(uint32_t*)&h1 };
        Hrow[i] = pk;
    }
    __shared__ float red[8];
    #pragma unroll
    for (int o = 16; o; o >>= 1) s += __shfl_down_sync(~0u, s, o);
    if ((threadIdx.x & 31) == 0) red[threadIdx.x >> 5] = s;
    __syncthreads();
    if (threadIdx.x < 8) {
        float t = red[threadIdx.x];
        #pragma unroll
        for (int o = 4; o; o >>= 1) t += __shfl_down_sync(0xffu, t, o);
        if (threadIdx.x == 0) dinv[row] = rsqrtf(t + 1.0f);
    }
}

// ---------------------------------------------------------------------------
// Converters
// ---------------------------------------------------------------------------
__global__ void conv_x(const float4* __restrict__ x, uint2* __restrict__ xh, int n4) {
    for (int i = blockIdx.x * blockDim.x + threadIdx.x; i < n4; i += gridDim.x * blockDim.x) {
        float4 v = x[i];
        __half2 h0 = __floats2half2_rn(v.x, v.y);
        __half2 h1 = __floats2half2_rn(v.z, v.w);
        xh[i] = make_uint2(*(uint32_t*)&h0, *(uint32_t*)&h1);
    }
}
// Wt[n*K + k] = W[k*NCOL + n]  (W: [K, NCOL] row-major)
__global__ void conv_w(const float* __restrict__ W, __half* __restrict__ Wt,
                       int K, int NCOL) {
    int i = blockIdx.x * blockDim.x + threadIdx.x;
    if (i < K * NCOL) {
        int n = i / K, k = i % K;
        Wt[i] = __float2half_rn(W[(size_t)k * NCOL + n]);
    }
}

// ---------------------------------------------------------------------------
// Kernel: M = d ⊙ (Xh @ Wt^T) via mma.sync + ldmatrix
// Xh: fp16 [B*N, K] row-major; Wt: fp16 [NCOL, K] (k contig)
// outputs: fp32 out[m, NCOL], fp16 outT[bb][n][j]
// ---------------------------------------------------------------------------
template <int K, int NCOL>
__global__ void __launch_bounds__(256, 2) xw_mma(
    const __half* __restrict__ Xh, const __half* __restrict__ Wt,
    const float* __restrict__ dinv, float* __restrict__ out,
    __half* __restrict__ outT)
{
    constexpr int BK = 64, S = 3, ITERS = K / BK;
    extern __shared__ __align__(16) char smem[];
    uint32_t sbase = smem_u32(smem);
    const int tid = threadIdx.x, lane = tid & 31, wid = tid >> 5;
    const int wm = wid & 3, wn = wid >> 2, gid = lane >> 2, t4 = lane & 3;
    const int m0 = blockIdx.y * 128, n0 = blockIdx.x * 128;
    // ldmatrix lane offsets
    const int a_ro = lane & 15, a_co = (lane >> 4) * 8;
    const int b_ro = (lane & 7) + ((lane >> 4) << 3), b_co = ((lane >> 3) & 1) * 8;

    auto issue = [&](int chunk, int stage) {
        int k0 = chunk * BK;
        uint32_t a_s = sbase + stage * STAGEB, b_s = a_s + TILEB;
        #pragma unroll
        for (int i = 0; i < 4; i++) {
            int slot = tid + i * 256, row = slot >> 3, qh = (slot & 7) * 8;
            cp16(a_s + row * ROWB + qh * 2, Xh + (size_t)(m0 + row) * K + k0 + qh);
            cp16(b_s + row * ROWB + qh * 2, Wt + (size_t)(n0 + row) * K + k0 + qh);
        }
    };

    float acc[2][8][4] = {};
    issue(0, 0); cp_commit();
    issue(1, 1); cp_commit();
    for (int it = 0; it < ITERS; it++) {
        int stage = it % S;
        if (it + S - 1 < ITERS) issue(it + S - 1, (it + S - 1) % S);
        cp_commit();
        cp_wait<S - 1>();
        __syncthreads();
        uint32_t As = sbase + stage * STAGEB, Bs = As + TILEB;
        #pragma unroll
        for (int ks = 0; ks < 4; ks++) {
            int k0h = ks * 16;
            uint32_t afr[2][4], bfr[8][2];
            uint32_t ab = As + (wm * 32 + a_ro) * ROWB + (k0h + a_co) * 2;
            ldsm_x4(afr[0], ab);
            ldsm_x4(afr[1], ab + 16 * ROWB);
            #pragma unroll
            for (int nt = 0; nt < 8; nt += 2) {
                uint32_t q[4];
                ldsm_x4(q, Bs + (wn * 64 + nt * 8 + b_ro) * ROWB + (k0h + b_co) * 2);
                bfr[nt][0] = q[0]; bfr[nt][1] = q[1];
                bfr[nt + 1][0] = q[2]; bfr[nt + 1][1] = q[3];
            }
            #pragma unroll
            for (int mt = 0; mt < 2; mt++)
                #pragma unroll
                for (int nt = 0; nt < 8; nt++)
                    mma16816(acc[mt][nt], afr[mt], bfr[nt]);
        }
        __syncthreads();
    }
    #pragma unroll
    for (int mt = 0; mt < 2; mt++) {
        int mA = m0 + wm * 32 + mt * 16 + gid, mB = mA + 8;
        float dA = dinv[mA], dB = dinv[mB];
        int bb = mA >> 12;                       // same batch for mA, mB
        int jjA = mA & (NN - 1), jjB = mB & (NN - 1);
        #pragma unroll
        for (int nt = 0; nt < 8; nt++) {
            int n = n0 + wn * 64 + nt * 8 + 2 * t4;
            float2 vA = { acc[mt][nt][0] * dA, acc[mt][nt][1] * dA };
            float2 vB = { acc[mt][nt][2] * dB, acc[mt][nt][3] * dB };
            *(float2*)(out + (size_t)mA * NCOL + n) = vA;
            *(float2*)(out + (size_t)mB * NCOL + n) = vB;
            __half* T = outT + (size_t)bb * NCOL * NN;
            T[(size_t)(n)     * NN + jjA] = __float2half_rn(vA.x);
            T[(size_t)(n + 1) * NN + jjA] = __float2half_rn(vA.y);
            T[(size_t)(n)     * NN + jjB] = __float2half_rn(vB.x);
            T[(size_t)(n + 1) * NN + jjB] = __float2half_rn(vB.y);
        }
    }
}

// ---------------------------------------------------------------------------
// Kernel: out = epi( A_b @ M_b + M_b ), mma.sync + ldmatrix
// Ah: fp16 [NN,NN]/batch; Mt: fp16 [NCOL,NN]/batch; Mn: fp32 [NN,NCOL]/batch
// epi: (acc+self)*d + bias (,relu); HALF_OUT -> fp16 row-major, else fp32
// ---------------------------------------------------------------------------
template <int NCOL, bool RELU, bool HALF_OUT>
__global__ void __launch_bounds__(256, 2) agemm_mma(
    const __half* __restrict__ Ah, const __half* __restrict__ Mt,
    const float* __restrict__ Mn, const float* __restrict__ dinv,
    const float* __restrict__ bias, void* __restrict__ outp)
{
    constexpr int BK = 64, S = 3, ITERS = NN / BK;
    extern __shared__ __align__(16) char smem[];
    uint32_t sbase = smem_u32(smem);
    const int tid = threadIdx.x, lane = tid & 31, wid = tid >> 5;
    const int wm = wid & 3, wn = wid >> 2, gid = lane >> 2, t4 = lane & 3;
    const int b = blockIdx.z;
    const int m0 = blockIdx.y * 128, n0 = blockIdx.x * 128;
    const __half* Ab  = Ah + (size_t)b * NN * NN;
    const __half* Mtb = Mt + (size_t)b * NCOL * NN;
    const float*  Mnb = Mn + (size_t)b * NN * NCOL;
    const float*  db  = dinv + b * NN;
    const int a_ro = lane & 15, a_co = (lane >> 4) * 8;
    const int b_ro = (lane & 7) + ((lane >> 4) << 3), b_co = ((lane >> 3) & 1) * 8;

    auto issue = [&](int chunk, int stage) {
        int k0 = chunk * BK;
        uint32_t a_s = sbase + stage * STAGEB, b_s = a_s + TILEB;
        #pragma unroll
        for (int i = 0; i < 4; i++) {
            int slot = tid + i * 256, row = slot >> 3, qh = (slot & 7) * 8;
            cp16(a_s + row * ROWB + qh * 2, Ab  + (size_t)(m0 + row) * NN + k0 + qh);
            cp16(b_s + row * ROWB + qh * 2, Mtb + (size_t)(n0 + row) * NN + k0 + qh);
        }
    };

    float acc[2][8][4] = {};
    issue(0, 0); cp_commit();
    issue(1, 1); cp_commit();
    for (int it = 0; it < ITERS; it++) {
        int stage = it % S;
        if (it + S - 1 < ITERS) issue(it + S - 1, (it + S - 1) % S);
        cp_commit();
        cp_wait<S - 1>();
        __syncthreads();
        uint32_t As = sbase + stage * STAGEB, Bs = As + TILEB;
        #pragma unroll
        for (int ks = 0; ks < 4; ks++) {
            int k0h = ks * 16;
            uint32_t afr[2][4], bfr[8][2];
            uint32_t ab = As + (wm * 32 + a_ro) * ROWB + (k0h + a_co) * 2;
            ldsm_x4(afr[0], ab);
            ldsm_x4(afr[1], ab + 16 * ROWB);
            #pragma unroll
            for (int nt = 0; nt < 8; nt += 2) {
                uint32_t q[4];
                ldsm_x4(q, Bs + (wn * 64 + nt * 8 + b_ro) * ROWB + (k0h + b_co) * 2);
                bfr[nt][0] = q[0]; bfr[nt][1] = q[1];
                bfr[nt + 1][0] = q[2]; bfr[nt + 1][1] = q[3];
            }
            #pragma unroll
            for (int mt = 0; mt < 2; mt++)
                #pragma unroll
                for (int nt = 0; nt < 8; nt++)
                    mma16816(acc[mt][nt], afr[mt], bfr[nt]);
        }
        __syncthreads();
    }
    #pragma unroll
    for (int mt = 0; mt < 2; mt++) {
        int mA = m0 + wm * 32 + mt * 16 + gid, mB = mA + 8;
        float dA = db[mA], dB = db[mB];
        #pragma unroll
        for (int nt = 0; nt < 8; nt++) {
            int n = n0 + wn * 64 + nt * 8 + 2 * t4;
            float2 bs = *(const float2*)(bias + n);
            float2 sA = *(const float2*)(Mnb + (size_t)mA * NCOL + n);
            float2 sB = *(const float2*)(Mnb + (size_t)mB * NCOL + n);
            float2 vA, vB;
            vA.x = (acc[mt][nt][0] + sA.x) * dA + bs.x;
            vA.y = (acc[mt][nt][1] + sA.y) * dA + bs.y;
            vB.x = (acc[mt][nt][2] + sB.x) * dB + bs.x;
            vB.y = (acc[mt][nt][3] + sB.y) * dB + bs.y;
            if (RELU) {
                vA.x = fmaxf(vA.x, 0.f); vA.y = fmaxf(vA.y, 0.f);
                vB.x = fmaxf(vB.x, 0.f); vB.y = fmaxf(vB.y, 0.f);
            }
            if (HALF_OUT) {
                __half* O = (__half*)outp + (size_t)b * NN * NCOL;
                __half2 hA = __floats2half2_rn(vA.x, vA.y);
                __half2 hB = __floats2half2_rn(vB.x, vB.y);
                *(__half2*)(O + (size_t)mA * NCOL + n) = hA;
                *(__half2*)(O + (size_t)mB * NCOL + n) = hB;
            } else {
                float* O = (float*)outp + (size_t)b * NN * NCOL;
                *(float2*)(O + (size_t)mA * NCOL + n) = vA;
                *(float2*)(O + (size_t)mB * NCOL + n) = vB;
            }
        }
    }
}

// ---------------------------------------------------------------------------
// Launch
// ---------------------------------------------------------------------------
extern "C" void kernel_launch(void* const* d_in, const int* in_sizes, int n_in,
                              void* d_out, int out_size)
{
    const float* x  = (const float*)d_in[0];
    const float* A  = (const float*)d_in[1];
    const float* W1 = (const float*)d_in[2];
    const float* b1 = (const float*)d_in[3];
    const float* W2 = (const float*)d_in[4];
    const float* b2 = (const float*)d_in[5];
    float* out = (float*)d_out;

    float*  dinv; cudaGetSymbolAddress((void**)&dinv, g_dinv);
    __half* Ah;   cudaGetSymbolAddress((void**)&Ah,   g_Ah);
    __half* xh;   cudaGetSymbolAddress((void**)&xh,   g_xh);
    __half* w1t;  cudaGetSymbolAddress((void**)&w1t,  g_w1t);
    __half* w2t;  cudaGetSymbolAddress((void**)&w2t,  g_w2t);
    float*  m1;   cudaGetSymbolAddress((void**)&m1,   g_m1);
    __half* m1t;  cudaGetSymbolAddress((void**)&m1t,  g_m1t);
    __half* hh;   cudaGetSymbolAddress((void**)&hh,   g_hh);
    float*  m2;   cudaGetSymbolAddress((void**)&m2,   g_m2);
    __half* m2t;  cudaGetSymbolAddress((void**)&m2t,  g_m2t);

    cudaFuncSetAttribute(xw_mma<INC, HIDC>,
                         cudaFuncAttributeMaxDynamicSharedMemorySize, SMEM_BYTES);
    cudaFuncSetAttribute(xw_mma<HIDC, OUTC>,
                         cudaFuncAttributeMaxDynamicSharedMemorySize, SMEM_BYTES);
    cudaFuncSetAttribute(agemm_mma<HIDC, true, true>,
                         cudaFuncAttributeMaxDynamicSharedMemorySize, SMEM_BYTES);
    cudaFuncSetAttribute(agemm_mma<OUTC, false, false>,
                         cudaFuncAttributeMaxDynamicSharedMemorySize, SMEM_BYTES);

    // 1. degrees + fp16 A
    deg_kernel<<<BATCH * NN, 256>>>(A, dinv, Ah);
    // 2. converts
    conv_x<<<2048, 256>>>((const float4*)x, (uint2*)xh, BATCH * NN * INC / 4);
    conv_w<<<(HIDC * INC + 255) / 256, 256>>>(W1, w1t, INC, HIDC);
    conv_w<<<(OUTC * HIDC + 255) / 256, 256>>>(W2, w2t, HIDC, OUTC);
    // 3. M1 = d ⊙ (x @ W1)
    {
        dim3 grid(HIDC / 128, BATCH * NN / 128);
        xw_mma<INC, HIDC><<<grid, 256, SMEM_BYTES>>>(xh, w1t, dinv, m1, m1t);
    }
    // 4. h = relu(d ⊙ (A@M1 + M1) + b1) -> fp16
    {
        dim3 grid(HIDC / 128, NN / 128, BATCH);
        agemm_mma<HIDC, true, true><<<grid, 256, SMEM_BYTES>>>(Ah, m1t, m1, dinv, b1, hh);
    }
    // 5. M2 = d ⊙ (h @ W2)
    {
        dim3 grid(OUTC / 128, BATCH * NN / 128);
        xw_mma<HIDC, OUTC><<<grid, 256, SMEM_BYTES>>>(hh, w2t, dinv, m2, m2t);
    }
    // 6. out = d ⊙ (A@M2 + M2) + b2
    {
        dim3 grid(OUTC / 128, NN / 128, BATCH);
        agemm_mma<OUTC, false, false><<<grid, 256, SMEM_BYTES>>>(Ah, m2t, m2, dinv, b2, out);
    }
}